// round 16
// baseline (speedup 1.0000x reference)
#include <cuda_runtime.h>
#include <cstdint>

// CoExCostVolume: cost[b,d,h,w] = sum_c x[b,c,h,w]*y[b,c,h,w-d], zero for w<d.
// B=8, C=96, H=128, W=416, D=49.
//
// One CTA per (b,h) row, 576 threads = 18 warps = 9 warp-pairs; pair g owns
// d in [6g, 6g+6) (g=8: only d=48 stored), lane index l (<52) owns w in
// [8l, 8l+8). d-tile 6 keeps d-tile-7's crossbar ratio (6 LDS.128 / 48 FFMA)
// while 18 warps fit the RF (48 accs), attacking the 14-warp latency wall.
// XOR swizzle S(p)=p^((p>>3)&4): 16B-alignment preserving, conflict-free for
// lane-stride-8-float LDS.128; every 16B vector uses its own swizzled address.
// Window phase R=(51-6g)&3 in {1,3}: two accum variants.
// cp.async(8B) 2-buffer depth-1 pipeline, 4 chunks of 24 channels.
// R16 fix: staging advance for 576 threads is +2 rows +160 (R15 used +80,
// misplacing a band of every chunk -> rel_err 0.30).

#define B_DIM 8
#define C_DIM 96
#define H_DIM 128
#define W_DIM 416
#define D_DIM 49
#define HW (H_DIM * W_DIM)

#define CC 24
#define NC 4
#define NBUF 2
#define PAD 56
#define XSTRIDE 448
#define YSTRIDE 480
#define XSZ (CC * XSTRIDE)
#define BUFSZ (XSZ + CC * YSTRIDE)      // 22272 floats
#define NTHREADS 576
#define SMEM_BYTES (NBUF * BUFSZ * 4)   // 178176

__device__ __forceinline__ int SW(int p) { return p ^ ((p >> 3) & 4); }

__device__ __forceinline__ void cp8(float* dst_smem, const float* src) {
    unsigned s = (unsigned)__cvta_generic_to_shared(dst_smem);
    asm volatile("cp.async.ca.shared.global [%0], [%1], 8;\n" ::"r"(s), "l"(src));
}

// One 24-channel chunk. R = window phase (warp-uniform, 1 or 3).
// acc(i,j) += x[w0+j] * y_pad[qa + R + 5 - i + j]; indices span [R, R+12].
template <int R>
__device__ __forceinline__ void accum(const float* __restrict__ buf,
                                      int xo0, int xo1,
                                      const int* __restrict__ yo,
                                      float* __restrict__ acc) {
#pragma unroll 6
    for (int c = 0; c < CC; c++) {
        float4 xa = *(const float4*)(buf + xo0 + c * XSTRIDE);
        float4 xc = *(const float4*)(buf + xo1 + c * XSTRIDE);
        float xv[8] = {xa.x, xa.y, xa.z, xa.w, xc.x, xc.y, xc.z, xc.w};

        float f[16];
#pragma unroll
        for (int v = 0; v < 4; v++) {
            float4 q = *(const float4*)(buf + yo[v] + c * YSTRIDE);
            f[4 * v + 0] = q.x; f[4 * v + 1] = q.y;
            f[4 * v + 2] = q.z; f[4 * v + 3] = q.w;
        }

#pragma unroll
        for (int i = 0; i < 6; i++)
#pragma unroll
            for (int j = 0; j < 8; j++)
                acc[i * 8 + j] = fmaf(xv[j], f[R + 5 - i + j], acc[i * 8 + j]);
    }
}

__global__ void __launch_bounds__(NTHREADS)
coex_cost_kernel(const float* __restrict__ x,
                 const float* __restrict__ y,
                 float* __restrict__ out) {
    extern __shared__ float sm[];

    const int bid = blockIdx.x;
    const int b = bid >> 7;
    const int h = bid & 127;
    const int tid = threadIdx.x;
    const int wid = tid >> 5;               // 0..17
    const int lane = tid & 31;
    const int g = wid >> 1;                 // 0..8 d-group (warp-uniform)
    const int l = ((wid & 1) << 5) + lane;  // 0..63
    const bool active = (l < 52);
    const int d0 = 6 * g;                   // 0,6,...,48
    const int w0 = 8 * l;

    const long rowb = ((long)(b * C_DIM) * H_DIM + h) * W_DIM;

    // ---- zero y left-pad once (all buffers); SW maps [0,PAD) to itself ----
    for (int i = tid; i < NBUF * CC * PAD; i += NTHREADS) {
        int buf = i / (CC * PAD);
        int rest = i - buf * (CC * PAD);
        int c = rest / PAD;
        int p = rest - c * PAD;
        sm[buf * BUFSZ + XSZ + c * YSTRIDE + p] = 0.0f;
    }

    // ---- per-thread addresses ----
    // window base (padded coords): q0 = w0 + PAD - 5 - d0 = w0 + 51 - 6g
    const int w0c = active ? w0 : 0;
    const int q0c = active ? (w0 + 51 - d0) : 3;   // inactive: harmless R=3
    const int R = q0c & 3;                          // 1 or 3, warp-uniform
    const int qa = q0c - R;
    const int xo0 = SW(w0c);
    const int xo1 = SW(w0c + 4);                    // own swizzle — NOT xo0+4
    int yo[4];
#pragma unroll
    for (int v = 0; v < 4; v++) yo[v] = XSZ + SW(qa + 4 * v);

    float acc[48];
#pragma unroll
    for (int i = 0; i < 48; i++) acc[i] = 0.0f;

    // ---- staging: additive (c, p) advance, 8B cp.async for x and y ----
    const int c0 = tid / 208;            // 0..2
    const int p0 = tid - c0 * 208;       // float2 index within row (<= 159)
    auto stage = [&](int k) {
        float* bx = sm + (k & (NBUF - 1)) * BUFSZ;
        float* by = bx + XSZ;
        const float* xg = x + rowb + (long)k * CC * HW;
        const float* yg = y + rowb + (long)k * CC * HW;
        int c = c0, p = p0;
#pragma unroll 1
        for (int it = 0; it < 9; it++) {
            if (c < CC) {
                int w = 2 * p;
                long gsrc = (long)c * HW + w;
                cp8(bx + c * XSTRIDE + SW(w), xg + gsrc);
                cp8(by + c * YSTRIDE + SW(PAD + w), yg + gsrc);
            }
            c += 2; p += 160;                // +576 float2 = 2 rows + 160
            if (p >= 208) { p -= 208; c += 1; }
        }
    };

    stage(0); asm volatile("cp.async.commit_group;\n");

#pragma unroll 1
    for (int k = 0; k < NC; k++) {
        asm volatile("cp.async.wait_group 0;\n" ::: "memory");
        __syncthreads();

        if (k + 1 < NC) {
            stage(k + 1);
            asm volatile("cp.async.commit_group;\n");
        }

        const float* buf = sm + (k & (NBUF - 1)) * BUFSZ;
        if (active) {
            if (R == 1) accum<1>(buf, xo0, xo1, yo, acc);
            else        accum<3>(buf, xo0, xo1, yo, acc);
        }
        __syncthreads();
    }

    // ---- stores: 6 d x 8 w per active thread (g=8 stores d=48 only) ----
    if (active) {
        const int ndi = (g < 8) ? 6 : 1;
#pragma unroll
        for (int i = 0; i < 6; i++) {
            if (i < ndi) {
                const int d = d0 + i;
                float* o = out + (((long)b * D_DIM + d) * H_DIM + h) * W_DIM + w0;
                *reinterpret_cast<float4*>(o) =
                    make_float4(acc[i * 8 + 0], acc[i * 8 + 1], acc[i * 8 + 2], acc[i * 8 + 3]);
                *reinterpret_cast<float4*>(o + 4) =
                    make_float4(acc[i * 8 + 4], acc[i * 8 + 5], acc[i * 8 + 6], acc[i * 8 + 7]);
            }
        }
    }
}

extern "C" void kernel_launch(void* const* d_in, const int* in_sizes, int n_in,
                              void* d_out, int out_size) {
    const float* x = (const float*)d_in[0];
    const float* y = (const float*)d_in[1];
    float* out = (float*)d_out;

    cudaFuncSetAttribute(coex_cost_kernel,
                         cudaFuncAttributeMaxDynamicSharedMemorySize, SMEM_BYTES);

    coex_cost_kernel<<<B_DIM * H_DIM, NTHREADS, SMEM_BYTES>>>(x, y, out);
}

// round 17
// speedup vs baseline: 1.2883x; 1.2883x over previous
#include <cuda_runtime.h>
#include <cstdint>

// CoExCostVolume via legacy tensor-core GEMM (mma.sync m16n8k8 tf32, 3-term
// hi/lo split for fp32-grade accuracy).
// cost[b,d,h,w] = sum_c x[b,c,h,w]*y[b,c,h,w-d] = band of C[w,w'] = X^T Y.
// One CTA per (b,h): 416 threads = 13 warps; warp wp owns m16 tiles at
// w0 = 32wp and 32wp+16. Each tile: 8 n8 tiles covering w' in [w0-48, w0+16);
// adjacent tiles share B-frags (10 distinct n8 positions per warp).
// K = 96 channels = 12 chunks of 8 (one k8 step each). Staging converts fp32 ->
// (tf32_hi, tf32_lo) pairs in smem; per (kstep, tile, n8): 3 mma accumulate
// xh*yh + xl*yh + xh*yl in fp32 (error ~2e-6). Double-buffered smem (56KB/buf),
// register-prefetched LDG covers global latency.
// Strides XS=424 (==8 mod 32), YS=472 (==24 mod 32) make all fragment LDS
// bank-conflict-free. Epilogue: predicated scattered STG.32 (coverage of all
// 49x416 outputs is bijective: 8j+ncol = mrow+48-d spans [0,63]).

#define B_DIM 8
#define C_DIM 96
#define H_DIM 128
#define W_DIM 416
#define D_DIM 49
#define HW (H_DIM * W_DIM)

#define KC 8                   // channels per chunk = one k8 step
#define NCH 12
#define XS 424                 // X smem stride (>=416, ==8 mod 32)
#define YS 472                 // Y smem stride (>=464, ==24 mod 32)
#define XHI 0
#define XLO (KC * XS)          // 3392
#define YHI (2 * KC * XS)      // 6784
#define YLO (2 * KC * XS + KC * YS)       // 10560
#define BUFSZ (2 * KC * XS + 2 * KC * YS) // 14336 floats = 57344 B
#define NTHREADS 416
#define SMEM_BYTES (2 * BUFSZ * 4)        // 114688 B

__device__ __forceinline__ uint32_t f2tf(float f) {
    uint32_t u;
    asm("cvt.rna.tf32.f32 %0, %1;" : "=r"(u) : "f"(f));
    return u;
}

#define MMA(c0, c1, c2, c3, a0, a1, a2, a3, b0, b1)                          \
    asm volatile(                                                            \
        "mma.sync.aligned.m16n8k8.row.col.f32.tf32.tf32.f32 "                \
        "{%0,%1,%2,%3}, {%4,%5,%6,%7}, {%8,%9}, {%0,%1,%2,%3};\n"            \
        : "+f"(c0), "+f"(c1), "+f"(c2), "+f"(c3)                             \
        : "r"(a0), "r"(a1), "r"(a2), "r"(a3), "r"(b0), "r"(b1))

__global__ void __launch_bounds__(NTHREADS)
coex_cost_mma(const float* __restrict__ x,
              const float* __restrict__ y,
              float* __restrict__ out) {
    extern __shared__ float sm[];

    const int bid = blockIdx.x;
    const int b = bid >> 7;
    const int h = bid & 127;
    const int tid = threadIdx.x;
    const int wp = tid >> 5;          // 0..12
    const int lane = tid & 31;
    const int g = lane >> 2;          // groupID 0..7
    const int tig = lane & 3;         // thread-in-group 0..3
    const int w0 = 32 * wp;           // pair base; tiles at w0 and w0+16

    const long rowb = (long)b * C_DIM * HW + (long)h * W_DIM;

    // thread-constant fragment offsets
    const int aoff = tig * XS + g;    // A: + w0(+16mt) (+8) (+4*XS)
    const int boff = tig * YS + g;    // B: + pb (+4*YS)

    // staging decomposition (4 float2 of X and of Y per thread per chunk)
    int sc[4], swo[4];
#pragma unroll
    for (int i = 0; i < 4; i++) {
        int idx = tid + i * NTHREADS;         // 0..1663
        sc[i] = idx / 208;
        swo[i] = (idx - sc[i] * 208) * 2;
    }

    // ---- prefetch chunk 0 ----
    float2 rx[4], ry[4];
    {
        const float* xg = x + rowb;
        const float* yg = y + rowb;
#pragma unroll
        for (int i = 0; i < 4; i++) {
            long o = (long)sc[i] * HW + swo[i];
            rx[i] = *(const float2*)(xg + o);
            ry[i] = *(const float2*)(yg + o);
        }
    }

    // ---- zero Y left-pad (p<48), both buffers, hi and lo ----
    for (int i = tid; i < 1536; i += NTHREADS) {
        int bufi = i / 768;
        int r = i - bufi * 768;
        int arr = r / 384;
        int r2 = r - arr * 384;
        int c = r2 / 48;
        int p = r2 - c * 48;
        sm[bufi * BUFSZ + (arr ? YLO : YHI) + c * YS + p] = 0.0f;
    }

    // accumulators: [mt][j][r]
    float a0[8][4], a1[8][4];
#pragma unroll
    for (int j = 0; j < 8; j++)
#pragma unroll
        for (int r = 0; r < 4; r++) { a0[j][r] = 0.0f; a1[j][r] = 0.0f; }

#pragma unroll 1
    for (int k = 0; k < NCH; k++) {
        float* bb = sm + (k & 1) * BUFSZ;

        // ---- store prefetched chunk k (convert to tf32 hi/lo) ----
#pragma unroll
        for (int i = 0; i < 4; i++) {
            const int c = sc[i], w = swo[i];
            uint32_t xh0 = f2tf(rx[i].x), xh1 = f2tf(rx[i].y);
            uint32_t xl0 = f2tf(rx[i].x - __uint_as_float(xh0));
            uint32_t xl1 = f2tf(rx[i].y - __uint_as_float(xh1));
            uint32_t yh0 = f2tf(ry[i].x), yh1 = f2tf(ry[i].y);
            uint32_t yl0 = f2tf(ry[i].x - __uint_as_float(yh0));
            uint32_t yl1 = f2tf(ry[i].y - __uint_as_float(yh1));
            *(uint2*)(bb + XHI + c * XS + w) = make_uint2(xh0, xh1);
            *(uint2*)(bb + XLO + c * XS + w) = make_uint2(xl0, xl1);
            *(uint2*)(bb + YHI + c * YS + 48 + w) = make_uint2(yh0, yh1);
            *(uint2*)(bb + YLO + c * YS + 48 + w) = make_uint2(yl0, yl1);
        }

        // ---- prefetch chunk k+1 ----
        if (k + 1 < NCH) {
            const float* xg = x + rowb + (long)(k + 1) * KC * HW;
            const float* yg = y + rowb + (long)(k + 1) * KC * HW;
#pragma unroll
            for (int i = 0; i < 4; i++) {
                long o = (long)sc[i] * HW + swo[i];
                rx[i] = *(const float2*)(xg + o);
                ry[i] = *(const float2*)(yg + o);
            }
        }
        __syncthreads();

        // ---- A fragments for both tiles (hi and lo) ----
        uint32_t ah[2][4], al[2][4];
#pragma unroll
        for (int mt = 0; mt < 2; mt++) {
            const int base = aoff + w0 + 16 * mt;
            ah[mt][0] = __float_as_uint(bb[XHI + base]);
            ah[mt][1] = __float_as_uint(bb[XHI + base + 8]);
            ah[mt][2] = __float_as_uint(bb[XHI + base + 4 * XS]);
            ah[mt][3] = __float_as_uint(bb[XHI + base + 4 * XS + 8]);
            al[mt][0] = __float_as_uint(bb[XLO + base]);
            al[mt][1] = __float_as_uint(bb[XLO + base + 8]);
            al[mt][2] = __float_as_uint(bb[XLO + base + 4 * XS]);
            al[mt][3] = __float_as_uint(bb[XLO + base + 4 * XS + 8]);
        }

        // ---- shared B walk: jj = 0..9; tile0 uses jj<8, tile1 uses jj>=2 ----
#pragma unroll
        for (int jj = 0; jj < 10; jj++) {
            const int pb = boff + w0 + 8 * jj;
            uint32_t bh0 = __float_as_uint(bb[YHI + pb]);
            uint32_t bh1 = __float_as_uint(bb[YHI + pb + 4 * YS]);
            uint32_t bl0 = __float_as_uint(bb[YLO + pb]);
            uint32_t bl1 = __float_as_uint(bb[YLO + pb + 4 * YS]);
            if (jj < 8) {
                MMA(a0[jj][0], a0[jj][1], a0[jj][2], a0[jj][3],
                    ah[0][0], ah[0][1], ah[0][2], ah[0][3], bh0, bh1);
                MMA(a0[jj][0], a0[jj][1], a0[jj][2], a0[jj][3],
                    al[0][0], al[0][1], al[0][2], al[0][3], bh0, bh1);
                MMA(a0[jj][0], a0[jj][1], a0[jj][2], a0[jj][3],
                    ah[0][0], ah[0][1], ah[0][2], ah[0][3], bl0, bl1);
            }
            if (jj >= 2) {
                const int j = jj - 2;
                MMA(a1[j][0], a1[j][1], a1[j][2], a1[j][3],
                    ah[1][0], ah[1][1], ah[1][2], ah[1][3], bh0, bh1);
                MMA(a1[j][0], a1[j][1], a1[j][2], a1[j][3],
                    al[1][0], al[1][1], al[1][2], al[1][3], bh0, bh1);
                MMA(a1[j][0], a1[j][1], a1[j][2], a1[j][3],
                    ah[1][0], ah[1][1], ah[1][2], ah[1][3], bl0, bl1);
            }
        }
        __syncthreads();
    }

    // ---- epilogue: predicated scattered stores ----
    // C[mrow][ncol] of tile (mt, j): w = w0+16mt+mrow, d = mrow+48-8j-ncol.
#pragma unroll
    for (int mt = 0; mt < 2; mt++) {
        const int wbase = w0 + 16 * mt;
#pragma unroll
        for (int j = 0; j < 8; j++)
#pragma unroll
            for (int r = 0; r < 4; r++) {
                const int mrow = g + ((r >> 1) << 3);
                const int ncol = 2 * tig + (r & 1);
                const int w = wbase + mrow;
                const int d = mrow + 48 - 8 * j - ncol;
                if (d >= 0 && d <= 48)
                    out[((long)(b * D_DIM + d) * H_DIM + h) * W_DIM + w] =
                        mt ? a1[j][r] : a0[j][r];
            }
    }
}

extern "C" void kernel_launch(void* const* d_in, const int* in_sizes, int n_in,
                              void* d_out, int out_size) {
    const float* x = (const float*)d_in[0];
    const float* y = (const float*)d_in[1];
    float* out = (float*)d_out;

    cudaFuncSetAttribute(coex_cost_mma,
                         cudaFuncAttributeMaxDynamicSharedMemorySize, SMEM_BYTES);

    coex_cost_mma<<<B_DIM * H_DIM, NTHREADS, SMEM_BYTES>>>(x, y, out);
}